// round 1
// baseline (speedup 1.0000x reference)
#include <cuda_runtime.h>
#include <cstdint>

#define NN 4096
#define BB 32

#define C_VTH    1.0f
#define C_ALPHA  0.025f
#define C_BETA   0.00025f
#define C_TNOW   10.0f
#define C_INVTV  0.9801986733067553f   /* exp(-1/50) */
#define C_INVTI  0.36787944117144233f  /* exp(-1)    */

// ---- scratch (__device__ globals; no allocation allowed) ----
__device__ uint32_t g_smask[NN];
__device__ uint32_t g_spany[NN];
__device__ float    g_maxst[NN];
__device__ float    g_y1[BB * NN];   // S @ W_new
__device__ float    g_y2[BB * NN];   // S @ W_new^T

// ---------------------------------------------------------------------------
// Kernel 1: per-neuron setup (spike bitmasks, max_st, sp_any) + zero y1/y2
// ---------------------------------------------------------------------------
__global__ void k_setup(const float* __restrict__ mem_pot,
                        const float* __restrict__ mem_pot_p,
                        const float* __restrict__ st) {
    int n = blockIdx.x * blockDim.x + threadIdx.x;
    if (n >= NN) return;
    uint32_t sm = 0u, spm = 0u;
#pragma unroll
    for (int b = 0; b < BB; b++) {
        // S: ceil(mp - 1) clipped -> spike iff (mp - 1) > 0
        if ((mem_pot[b * NN + n] - C_VTH) > 0.0f)                 sm  |= (1u << b);
        // S_paired: ((mpp - 1) - alpha) > 0  (match jax op order)
        if (((mem_pot_p[b * NN + n] - C_VTH) - C_ALPHA) > 0.0f)   spm |= (1u << b);
    }
    g_smask[n] = sm;
    g_spany[n] = (spm != 0u) ? 1u : 0u;
    float s = st[n];
    float mst;
    if (sm == 0u)               mst = s;            // no spike anywhere: keep st
    else if (sm == 0xFFFFFFFFu) mst = C_TNOW;       // all batches spiked
    else                        mst = fmaxf(C_TNOW, s);
    g_maxst[n] = mst;
#pragma unroll
    for (int b = 0; b < BB; b++) {
        g_y1[b * NN + n] = 0.0f;
        g_y2[b * NN + n] = 0.0f;
    }
}

// ---------------------------------------------------------------------------
// Kernel 2: fused W update + binary GEMM partials.
// Tile 128x128 of W. Phase 1: stream rows -> compute W_new, write gmem + smem
// tile, accumulate y1 (thread-per-column, 32 batch accumulators, row masks
// uniform). Phase 2: read smem tile transposed -> accumulate y2.
// ---------------------------------------------------------------------------
constexpr int TR = 128;
constexpr int TC = 128;
constexpr int K2_THREADS = 256;
// dynamic smem layout: tile[TR][TC+1] | rmask[TR] | rmaxst[TR] | ralpha[TR] | cmask[TC]
constexpr int SMEM_BYTES = TR * (TC + 1) * 4 + TR * 4 * 3 + TC * 4;

extern __shared__ float s_dyn[];

__global__ void __launch_bounds__(K2_THREADS, 3)
k_wpass(const float* __restrict__ W, float* __restrict__ Wn) {
    float (*tile)[TC + 1] = (float (*)[TC + 1])s_dyn;
    uint32_t* rmask  = (uint32_t*)(s_dyn + TR * (TC + 1));
    float*    rmaxst = (float*)(rmask + TR);
    float*    ralpha = rmaxst + TR;
    uint32_t* cmask  = (uint32_t*)(ralpha + TR);

    const int c0 = blockIdx.x * TC;
    const int r0 = blockIdx.y * TR;
    const int tid = threadIdx.x;

    for (int i = tid; i < TR; i += K2_THREADS) {
        int r = r0 + i;
        rmask[i]  = g_smask[r];
        rmaxst[i] = g_maxst[r];
        ralpha[i] = g_spany[r] ? C_ALPHA : 0.0f;
    }
    for (int i = tid; i < TC; i += K2_THREADS) cmask[i] = g_smask[c0 + i];
    __syncthreads();

    // ---- phase 1: W update + y1 ----
    {
        const int tc   = tid & (TC - 1);
        const int rbeg = (tid >> 7) * (TR / 2);     // 2 threads per column
        const int c    = c0 + tc;
        const float cmaxst = g_maxst[c];

        float acc[BB];
#pragma unroll
        for (int b = 0; b < BB; b++) acc[b] = 0.0f;

#pragma unroll 4
        for (int i = 0; i < TR / 2; i++) {
            const int tr = rbeg + i;
            const size_t idx = (size_t)(r0 + tr) * NN + c;
            const float w = W[idx];
            const float d = fabsf(rmaxst[tr] - cmaxst);
            const float sub = ralpha[tr] * __expf(d * (1.0f / 50.0f));
            float wn = fminf(fmaxf((w + C_BETA) - sub, 0.0f), 1.0f);
            wn = (w > 0.0f) ? wn : w;            // sign_mask select
            Wn[idx] = wn;
            tile[tr][tc] = wn;
            const uint32_t m = rmask[tr];
#pragma unroll
            for (int b = 0; b < BB; b++)
                if (m & (1u << b)) acc[b] += wn;
        }
#pragma unroll
        for (int b = 0; b < BB; b++) atomicAdd(&g_y1[b * NN + c], acc[b]);
    }
    __syncthreads();

    // ---- phase 2: y2 from transposed smem tile ----
    {
        const int trr  = tid & (TR - 1);
        const int cbeg = (tid >> 7) * (TC / 2);     // 2 threads per row
        float acc[BB];
#pragma unroll
        for (int b = 0; b < BB; b++) acc[b] = 0.0f;

#pragma unroll 4
        for (int i = 0; i < TC / 2; i++) {
            const int tc2 = cbeg + i;
            const float wn = tile[trr][tc2];        // stride TC+1 -> bank-conflict-free
            const uint32_t m = cmask[tc2];
#pragma unroll
            for (int b = 0; b < BB; b++)
                if (m & (1u << b)) acc[b] += wn;
        }
#pragma unroll
        for (int b = 0; b < BB; b++) atomicAdd(&g_y2[b * NN + (r0 + trr)], acc[b]);
    }
}

// ---------------------------------------------------------------------------
// Kernel 3: final elementwise integrate / leak / reset / refractory
// ---------------------------------------------------------------------------
__global__ void k_final(const float* __restrict__ inp,
                        const float* __restrict__ mem_pot,
                        const float* __restrict__ mem_cur,
                        const float* __restrict__ mem_pot_p,
                        const float* __restrict__ mem_cur_p,
                        const int*   __restrict__ refrac,
                        float* __restrict__ oS,  float* __restrict__ oMP,
                        float* __restrict__ oMC, float* __restrict__ oMPP,
                        float* __restrict__ oMCP, float* __restrict__ oRef) {
    int i = blockIdx.x * blockDim.x + threadIdx.x;
    if (i >= BB * NN) return;

    const float mp  = mem_pot[i];
    const float mpp = mem_pot_p[i];
    const bool S  = (mp - C_VTH) > 0.0f;
    const bool Sp = ((mpp - C_VTH) - C_ALPHA) > 0.0f;

    const int rf = refrac[i];
    const int rd = (rf > 0) ? (rf - 1) : rf;
    const bool active = (rd == 0);

    const float mc  = mem_cur[i];
    const float mcp = mem_cur_p[i];

    float mcn  = active ? ((inp[i] + g_y1[i]) + mc) : mc;
    float mcpn = active ? (g_y2[i] + mcp)           : mcp;
    float mpn  = active ? (mcn + mp)                : mp;
    float mppn = active ? (mcpn + mpp)              : mpp;

    mpn  *= C_INVTV;
    mcn  *= C_INVTI;
    mppn *= C_INVTV;
    mcpn *= C_INVTI;

    if (S)  mpn  = 0.0f;
    if (Sp) mppn = 0.0f;
    const int rnew = S ? 2 : rd;

    oS[i]   = S ? 1.0f : 0.0f;
    oMP[i]  = mpn;
    oMC[i]  = mcn;
    oMPP[i] = mppn;
    oMCP[i] = mcpn;
    oRef[i] = (float)rnew;
}

// ---------------------------------------------------------------------------
// Launch. Output: concat of [S, mem_pot_n, W_new, mem_cur_n, mem_pot_p_n,
// mem_cur_p_n, refrac_new] as float32 (jax weak promotion -> f32).
// ---------------------------------------------------------------------------
extern "C" void kernel_launch(void* const* d_in, const int* in_sizes, int n_in,
                              void* d_out, int out_size) {
    const float* inp  = (const float*)d_in[0];
    const float* W    = (const float*)d_in[1];
    const float* mp   = (const float*)d_in[2];
    const float* mc   = (const float*)d_in[3];
    const float* mpp  = (const float*)d_in[4];
    const float* mcp  = (const float*)d_in[5];
    const float* st   = (const float*)d_in[6];
    const int*   refr = (const int*)d_in[7];

    float* out  = (float*)d_out;
    float* oS   = out;
    float* oMP  = out + (size_t)BB * NN;
    float* oW   = out + (size_t)2 * BB * NN;
    float* oMC  = oW   + (size_t)NN * NN;
    float* oMPP = oMC  + (size_t)BB * NN;
    float* oMCP = oMPP + (size_t)BB * NN;
    float* oRef = oMCP + (size_t)BB * NN;

    cudaFuncSetAttribute(k_wpass, cudaFuncAttributeMaxDynamicSharedMemorySize,
                         SMEM_BYTES);

    k_setup<<<NN / 256, 256>>>(mp, mpp, st);

    dim3 g2(NN / TC, NN / TR);
    k_wpass<<<g2, K2_THREADS, SMEM_BYTES>>>(W, oW);

    k_final<<<(BB * NN) / 256, 256>>>(inp, mp, mc, mpp, mcp, refr,
                                      oS, oMP, oMC, oMPP, oMCP, oRef);
}